// round 9
// baseline (speedup 1.0000x reference)
#include <cuda_runtime.h>
#include <stdint.h>

#define Bn 8
#define Hn 1024
#define Wn 1024
#define HW (Hn * Wn)
#define Nn (Bn * Hn * Wn)
#define THRESH 1.5f
#define MIN_AREA_C 3
#define TPB 256
#define PPT 4
#define NT4 (Nn / PPT)
#define STRIP_ROWS 4
#define STRIP_PX (STRIP_ROWS * Wn)          // 4096 px per block
#define NSTRIPS (Nn / STRIP_PX)             // 2048 blocks
#define NBTHREADS ((Nn / STRIP_ROWS) / PPT) // boundary-row pixels / PPT

// Scratch in __device__ globals (no runtime allocation allowed).
__device__ int                g_parent[Nn];   // fg: union-find parent; bg: -1
__device__ unsigned long long g_agg[Nn];      // packed (val_bits<<32) | ~within
__device__ int                g_area[Nn];     // per-root pixel count

__device__ __forceinline__ unsigned long long pack_key(float v, int i) {
    unsigned int vb     = (unsigned int)__float_as_int(v);        // v>=1.5>0
    unsigned int within = (unsigned int)(i & (HW - 1));
    return ((unsigned long long)vb << 32) | (unsigned long long)(~within);
}

// ---------------------------------------------------------------------------
// Union-find. Roots only decrease (atomicMin links high -> low), so read-only
// find is race-safe during merge phases.
// ---------------------------------------------------------------------------
__device__ __forceinline__ int find_ro(int i) {
    int p;
    while ((p = g_parent[i]) != i) i = p;
    return i;
}

__device__ __forceinline__ void unite(int a, int b) {
    int ra = find_ro(a);
    int rb = find_ro(b);
    while (ra != rb) {
        if (ra < rb) { int t = ra; ra = rb; rb = t; }  // ra > rb
        int old = atomicMin(&g_parent[ra], rb);
        if (old == ra) break;
        ra = find_ro(old);
        rb = find_ro(rb);
    }
}

// ---------------------------------------------------------------------------
// K0 (fused init + intra-strip merge): each block owns a 4-row strip.
// Phase 1: threshold, write parent/agg/area, stash fg nibbles in smem.
// Phase 2: all unions fully inside the strip (left for all rows; vertical +
// diagonal for rows 1..3). Strip-top vertical unions are deferred to
// k_bmerge. All parent entries touched here were written by this block, so
// __syncthreads gives the needed ordering; union order doesn't matter.
// ---------------------------------------------------------------------------
__global__ void k_fused(const float* __restrict__ x) {
    __shared__ unsigned char fgs[STRIP_ROWS][TPB];   // fg nibble per thread/row
    const int strip = blockIdx.x;
    const int blockStart = strip * STRIP_PX;
    const int t = threadIdx.x;

    int fgn[STRIP_ROWS];
    #pragma unroll
    for (int j = 0; j < STRIP_ROWS; j++) {
        int base = blockStart + j * Wn + t * PPT;
        float4 v = *reinterpret_cast<const float4*>(x + base);
        int4 p;
        p.x = (v.x >= THRESH) ? base     : -1;
        p.y = (v.y >= THRESH) ? base + 1 : -1;
        p.z = (v.z >= THRESH) ? base + 2 : -1;
        p.w = (v.w >= THRESH) ? base + 3 : -1;
        *reinterpret_cast<int4*>(g_parent + base) = p;
        if (p.x >= 0) { g_agg[base]     = pack_key(v.x, base);     g_area[base]     = 0; }
        if (p.y >= 0) { g_agg[base + 1] = pack_key(v.y, base + 1); g_area[base + 1] = 0; }
        if (p.z >= 0) { g_agg[base + 2] = pack_key(v.z, base + 2); g_area[base + 2] = 0; }
        if (p.w >= 0) { g_agg[base + 3] = pack_key(v.w, base + 3); g_area[base + 3] = 0; }
        int nib = (p.x >= 0) | ((p.y >= 0) << 1) | ((p.z >= 0) << 2) | ((p.w >= 0) << 3);
        fgs[j][t] = (unsigned char)nib;
        fgn[j] = nib;
    }
    __syncthreads();

    #pragma unroll
    for (int j = 0; j < STRIP_ROWS; j++) {
        int nib = fgn[j];
        if (!nib) continue;
        int base = blockStart + j * Wn + t * PPT;
        int leftnib = (t > 0) ? fgs[j][t - 1] : 0;
        int upnib = 0, upl = 0, upr = 0;
        if (j > 0) {
            upnib = fgs[j - 1][t];
            upl = (t > 0)        ? fgs[j - 1][t - 1] : 0;
            upr = (t < TPB - 1)  ? fgs[j - 1][t + 1] : 0;
        }
        #pragma unroll
        for (int k = 0; k < PPT; k++) {
            if (!((nib >> k) & 1)) continue;
            int i = base + k;
            int lf = k ? ((nib >> (k - 1)) & 1) : ((leftnib >> 3) & 1);
            if (lf) unite(i, i - 1);
            if (j > 0) {
                if ((upnib >> k) & 1) {
                    unite(i, i - Wn);
                } else {           // Komura pruning: diagonals only if up is bg
                    int ul = k ? ((upnib >> (k - 1)) & 1) : ((upl >> 3) & 1);
                    int ur = (k < 3) ? ((upnib >> (k + 1)) & 1) : (upr & 1);
                    if (ul) unite(i, i - Wn - 1);
                    if (ur) unite(i, i - Wn + 1);
                }
            }
        }
    }
}

// ---------------------------------------------------------------------------
// K1: boundary merge — only strip-top rows (row % 4 == 0), vertical/diagonal
// unions into the strip above. Left unions were already done in k_fused.
// Skips image-top rows. 1/4 of the pixels of the old full merge pass.
// ---------------------------------------------------------------------------
__global__ void k_bmerge() {
    int t = blockIdx.x * blockDim.x + threadIdx.x;
    if (t >= NBTHREADS) return;
    int row_id = (t * PPT) >> 10;          // which boundary row (0..2047)
    if ((row_id & (Hn / STRIP_ROWS - 1)) == 0) return;   // image top row
    int c0 = (t * PPT) & (Wn - 1);
    int base = row_id * STRIP_PX + c0;     // global index in row 4*row_id

    int4 pc = *reinterpret_cast<const int4*>(g_parent + base);
    int fgc[PPT] = { pc.x >= 0, pc.y >= 0, pc.z >= 0, pc.w >= 0 };
    if (!(fgc[0] | fgc[1] | fgc[2] | fgc[3])) return;

    int up[PPT + 2];
    int4 pu = *reinterpret_cast<const int4*>(g_parent + base - Wn);
    up[1] = pu.x; up[2] = pu.y; up[3] = pu.z; up[4] = pu.w;
    up[0] = (c0 > 0)        ? g_parent[base - Wn - 1]   : -1;
    up[5] = (c0 < Wn - PPT) ? g_parent[base - Wn + PPT] : -1;

    #pragma unroll
    for (int k = 0; k < PPT; k++) {
        if (!fgc[k]) continue;
        int i = base + k;
        if (up[k + 1] >= 0) {
            unite(i, i - Wn);
        } else {
            if (up[k] >= 0)     unite(i, i - Wn - 1);
            if (up[k + 2] >= 0) unite(i, i - Wn + 1);
        }
    }
}

// ---------------------------------------------------------------------------
// K2: aggregate + path compression. Key from pre-seeded agg[i] (L2-resident).
// Compressed parent written back only when changed.
// ---------------------------------------------------------------------------
__global__ void k_aggregate() {
    int t = blockIdx.x * blockDim.x + threadIdx.x;
    if (t >= NT4) return;
    int base = t * PPT;
    int4 pc = *reinterpret_cast<const int4*>(g_parent + base);
    int pv[PPT] = { pc.x, pc.y, pc.z, pc.w };
    if (pv[0] < 0 && pv[1] < 0 && pv[2] < 0 && pv[3] < 0) return;

    int roots[PPT];
    #pragma unroll
    for (int k = 0; k < PPT; k++)
        roots[k] = (pv[k] >= 0) ? find_ro(base + k) : -1;

    #pragma unroll
    for (int k = 0; k < PPT; k++) {
        if (roots[k] < 0) continue;
        int i = base + k;
        atomicAdd(&g_area[roots[k]], 1);
        if (roots[k] != i)
            atomicMax(&g_agg[roots[k]], g_agg[i]);
    }

    int4 nc = make_int4(roots[0], roots[1], roots[2], roots[3]);
    if (nc.x != pc.x || nc.y != pc.y || nc.z != pc.z || nc.w != pc.w)
        *reinterpret_cast<int4*>(g_parent + base) = nc;
}

// ---------------------------------------------------------------------------
// K3: emit dense (max,row,col) float32, 4 px/thread, streaming stores.
// ---------------------------------------------------------------------------
__global__ void k_emit(float* __restrict__ out, int write_rc) {
    int t = blockIdx.x * blockDim.x + threadIdx.x;
    if (t >= NT4) return;
    int base = t * PPT;
    int4 pc = *reinterpret_cast<const int4*>(g_parent + base);
    int pv[PPT] = { pc.x, pc.y, pc.z, pc.w };

    int ar[PPT];
    #pragma unroll
    for (int k = 0; k < PPT; k++)
        ar[k] = (pv[k] >= 0) ? __ldg(&g_area[pv[k]]) : 0;

    float mx[PPT], rw[PPT], cl[PPT];
    #pragma unroll
    for (int k = 0; k < PPT; k++) {
        mx[k] = 0.0f; rw[k] = -1.0f; cl[k] = -1.0f;
        if (pv[k] >= 0 && ar[k] > MIN_AREA_C) {
            unsigned long long key = __ldg(&g_agg[pv[k]]);
            mx[k] = __int_as_float((int)(unsigned int)(key >> 32));
            unsigned int within = ~(unsigned int)(key & 0xFFFFFFFFull);
            rw[k] = (float)(within >> 10);
            cl[k] = (float)(within & (Wn - 1));
        }
    }
    __stcs(reinterpret_cast<float4*>(out + base),
           make_float4(mx[0], mx[1], mx[2], mx[3]));
    if (write_rc) {
        __stcs(reinterpret_cast<float4*>(out + Nn + base),
               make_float4(rw[0], rw[1], rw[2], rw[3]));
        __stcs(reinterpret_cast<float4*>(out + 2 * Nn + base),
               make_float4(cl[0], cl[1], cl[2], cl[3]));
    }
}

extern "C" void kernel_launch(void* const* d_in, const int* in_sizes, int n_in,
                              void* d_out, int out_size) {
    const float* x = (const float*)d_in[0];
    float* out = (float*)d_out;
    int write_rc = (out_size >= 3 * Nn) ? 1 : 0;

    k_fused<<<NSTRIPS, TPB>>>(x);
    k_bmerge<<<(NBTHREADS + TPB - 1) / TPB, TPB>>>();
    k_aggregate<<<(NT4 + TPB - 1) / TPB, TPB>>>();
    k_emit<<<(NT4 + TPB - 1) / TPB, TPB>>>(out, write_rc);
}